// round 2
// baseline (speedup 1.0000x reference)
#include <cuda_runtime.h>

// SphereConv: y[b,f,l,m] = relu/id( sqrt(1+l)/C * sum_c W[f,c,l] (*) x[b,c,l,m] )
// R2: split m per thread 4->2 to halve accumulator registers (128->~70),
// grid 256->512, launch_bounds(256,3) for ~2x occupancy; weights pre-packed
// as u64 in smem and read via LDS.128 (2 f's per load).

#define B_ 4
#define C_ 32
#define L_ 256
#define M_ 256
#define F_ 8
#define N_ 64

typedef unsigned long long u64;

__device__ __forceinline__ u64 pk2(float lo, float hi) {
    u64 r;
    asm("mov.b64 %0, {%1, %2};" : "=l"(r) : "f"(lo), "f"(hi));
    return r;
}
__device__ __forceinline__ void upk2(u64 v, float& lo, float& hi) {
    asm("mov.b64 {%0, %1}, %2;" : "=f"(lo), "=f"(hi) : "l"(v));
}
__device__ __forceinline__ u64 ffma2(u64 a, u64 b, u64 c) {
    u64 d;
    asm("fma.rn.f32x2 %0, %1, %2, %3;" : "=l"(d) : "l"(a), "l"(b), "l"(c));
    return d;
}

__global__ void __launch_bounds__(256, 3) sphere_conv_kernel(
    const float* __restrict__ xr, const float* __restrict__ xi,
    const float* __restrict__ wr, const float* __restrict__ wi,
    float* __restrict__ out)
{
    // f-contiguous so two adjacent f load as one LDS.128
    __shared__ u64 swr[C_ * F_];   // {s*wr, s*wr}
    __shared__ u64 swi[C_ * F_];   // {s*wi, s*wi}
    __shared__ u64 snw[C_ * F_];   // {-s*wi, -s*wi}

    const int l   = blockIdx.x;
    const int tid = threadIdx.x;

    // --- per-block weight interpolation (one (f,c) per thread) ---
    {
        const int f = tid >> 5;        // 0..7
        const int c = tid & 31;        // 0..31
        float t = ((float)l / (float)(L_ - 1)) * (float)(N_ - 1);
        int lo = (int)floorf(t);
        lo = lo < 0 ? 0 : (lo > N_ - 2 ? N_ - 2 : lo);
        const float fr = t - (float)lo;
        const int base = (f * C_ + c) * N_ + lo;
        float wrv = wr[base] * (1.0f - fr) + wr[base + 1] * fr;
        float wiv = wi[base] * (1.0f - fr) + wi[base + 1] * fr;
        const float s = sqrtf(1.0f + (float)l) * (1.0f / (float)C_);
        wrv *= s; wiv *= s;
        swr[c * F_ + f] = pk2(wrv, wrv);
        swi[c * F_ + f] = pk2(wiv, wiv);
        snw[c * F_ + f] = pk2(-wiv, -wiv);
    }
    __syncthreads();

    const int b  = tid >> 6;                        // 0..3
    const int mp = tid & 63;                        // m-pair within half
    const int m0 = (blockIdx.y << 7) + (mp << 1);   // 2 m-values per thread

    const int base2 = ((((b * C_) * L_ + l) * M_ + m0) >> 1);  // float2 index (c=0)
    const int cstr2 = (L_ * M_) >> 1;                          // float2 stride per c

    const float2* __restrict__ xr2 = (const float2*)xr;
    const float2* __restrict__ xi2 = (const float2*)xi;

    u64 aR[F_], aI[F_];
    #pragma unroll
    for (int f = 0; f < F_; ++f) { aR[f] = 0ull; aI[f] = 0ull; }

    #pragma unroll 4
    for (int c = 0; c < C_; ++c) {
        const float2 vr = __ldg(xr2 + base2 + c * cstr2);
        const float2 vi = __ldg(xi2 + base2 + c * cstr2);
        const u64 x_r = pk2(vr.x, vr.y);
        const u64 x_i = pk2(vi.x, vi.y);

        const ulonglong2* __restrict__ pwr = (const ulonglong2*)(swr + c * F_);
        const ulonglong2* __restrict__ pwi = (const ulonglong2*)(swi + c * F_);
        const ulonglong2* __restrict__ pnw = (const ulonglong2*)(snw + c * F_);

        #pragma unroll
        for (int fp = 0; fp < F_ / 2; ++fp) {
            const ulonglong2 w_r = pwr[fp];
            const ulonglong2 w_i = pwi[fp];
            const ulonglong2 w_n = pnw[fp];
            const int f0 = fp * 2;
            aR[f0]     = ffma2(w_r.x, x_r, aR[f0]);
            aR[f0]     = ffma2(w_n.x, x_i, aR[f0]);
            aI[f0]     = ffma2(w_r.x, x_i, aI[f0]);
            aI[f0]     = ffma2(w_i.x, x_r, aI[f0]);
            aR[f0 + 1] = ffma2(w_r.y, x_r, aR[f0 + 1]);
            aR[f0 + 1] = ffma2(w_n.y, x_i, aR[f0 + 1]);
            aI[f0 + 1] = ffma2(w_r.y, x_i, aI[f0 + 1]);
            aI[f0 + 1] = ffma2(w_i.y, x_r, aI[f0 + 1]);
        }
    }

    // --- epilogue: relu on real part only, write (2, B, F, L, M) ---
    const int outHalf = B_ * F_ * L_ * M_;
    #pragma unroll
    for (int f = 0; f < F_; ++f) {
        const int oR = ((b * F_ + f) * L_ + l) * M_ + m0;
        float r0, r1, i0, i1;
        upk2(aR[f], r0, r1);
        upk2(aI[f], i0, i1);
        *(float2*)(out + oR)           = make_float2(fmaxf(r0, 0.0f), fmaxf(r1, 0.0f));
        *(float2*)(out + outHalf + oR) = make_float2(i0, i1);
    }
}

extern "C" void kernel_launch(void* const* d_in, const int* in_sizes, int n_in,
                              void* d_out, int out_size) {
    const float* xr = (const float*)d_in[0];
    const float* xi = (const float*)d_in[1];
    const float* wr = (const float*)d_in[2];
    const float* wi = (const float*)d_in[3];
    float* out = (float*)d_out;
    dim3 grid(L_, 2);
    sphere_conv_kernel<<<grid, 256>>>(xr, xi, wr, wi, out);
}

// round 3
// speedup vs baseline: 1.2407x; 1.2407x over previous
#include <cuda_runtime.h>

// SphereConv R3: f-split. Each thread: 4 m (float4 LDG) x 4 f -> 16 u64 accums,
// ~70 regs, 3 CTAs/SM. Two blocks per l cover f-halves; duplicate x reads hit L2.
// Weights interpolated+scaled once per block, pre-packed u64 in smem, read as
// ulonglong2 (LDS.128, 3 per c for 4 f's).

#define B_ 4
#define C_ 32
#define L_ 256
#define M_ 256
#define F_ 8
#define N_ 64
#define FH 4   // f's per block

typedef unsigned long long u64;

__device__ __forceinline__ u64 pk2(float lo, float hi) {
    u64 r;
    asm("mov.b64 %0, {%1, %2};" : "=l"(r) : "f"(lo), "f"(hi));
    return r;
}
__device__ __forceinline__ void upk2(u64 v, float& lo, float& hi) {
    asm("mov.b64 {%0, %1}, %2;" : "=f"(lo), "=f"(hi) : "l"(v));
}
__device__ __forceinline__ u64 ffma2(u64 a, u64 b, u64 c) {
    u64 d;
    asm("fma.rn.f32x2 %0, %1, %2, %3;" : "=l"(d) : "l"(a), "l"(b), "l"(c));
    return d;
}

__global__ void __launch_bounds__(256, 3) sphere_conv_kernel(
    const float* __restrict__ xr, const float* __restrict__ xi,
    const float* __restrict__ wr, const float* __restrict__ wi,
    float* __restrict__ out)
{
    // f-contiguous within each c so 2 adjacent f load as one LDS.128
    __shared__ u64 swr[C_ * FH];   // {s*wr, s*wr}
    __shared__ u64 swi[C_ * FH];   // {s*wi, s*wi}
    __shared__ u64 snw[C_ * FH];   // {-s*wi, -s*wi}

    const int fh  = blockIdx.x;    // 0..1 f-half
    const int l   = blockIdx.y;
    const int tid = threadIdx.x;

    // --- per-block weight interpolation: 128 (f_local, c) pairs, threads 0..127 ---
    if (tid < C_ * FH) {
        const int fl = tid >> 5;       // 0..3
        const int c  = tid & 31;       // 0..31
        const int f  = fh * FH + fl;
        float t = ((float)l / (float)(L_ - 1)) * (float)(N_ - 1);
        int lo = (int)floorf(t);
        lo = lo < 0 ? 0 : (lo > N_ - 2 ? N_ - 2 : lo);
        const float fr = t - (float)lo;
        const int base = (f * C_ + c) * N_ + lo;
        float wrv = wr[base] * (1.0f - fr) + wr[base + 1] * fr;
        float wiv = wi[base] * (1.0f - fr) + wi[base + 1] * fr;
        const float s = sqrtf(1.0f + (float)l) * (1.0f / (float)C_);
        wrv *= s; wiv *= s;
        swr[c * FH + fl] = pk2(wrv, wrv);
        swi[c * FH + fl] = pk2(wiv, wiv);
        snw[c * FH + fl] = pk2(-wiv, -wiv);
    }
    __syncthreads();

    const int b  = tid >> 6;          // 0..3
    const int mq = tid & 63;          // 0..63
    const int m0 = mq << 2;           // 4 m-values per thread

    const int base4 = (((b * C_) * L_ + l) * M_ + m0) >> 2;  // float4 index (c=0)
    const int cstr4 = (L_ * M_) >> 2;

    const float4* __restrict__ xr4 = (const float4*)xr;
    const float4* __restrict__ xi4 = (const float4*)xi;

    u64 aR[FH][2], aI[FH][2];
    #pragma unroll
    for (int f = 0; f < FH; ++f) {
        aR[f][0] = aR[f][1] = 0ull;
        aI[f][0] = aI[f][1] = 0ull;
    }

    #pragma unroll 4
    for (int c = 0; c < C_; ++c) {
        const float4 vr = __ldg(xr4 + base4 + c * cstr4);
        const float4 vi = __ldg(xi4 + base4 + c * cstr4);
        const u64 x_r0 = pk2(vr.x, vr.y), x_r1 = pk2(vr.z, vr.w);
        const u64 x_i0 = pk2(vi.x, vi.y), x_i1 = pk2(vi.z, vi.w);

        const ulonglong2* __restrict__ pwr = (const ulonglong2*)(swr + c * FH);
        const ulonglong2* __restrict__ pwi = (const ulonglong2*)(swi + c * FH);
        const ulonglong2* __restrict__ pnw = (const ulonglong2*)(snw + c * FH);

        #pragma unroll
        for (int fp = 0; fp < FH / 2; ++fp) {
            const ulonglong2 w_r = pwr[fp];
            const ulonglong2 w_i = pwi[fp];
            const ulonglong2 w_n = pnw[fp];
            const int f0 = fp * 2;
            aR[f0][0]     = ffma2(w_r.x, x_r0, aR[f0][0]);
            aR[f0][0]     = ffma2(w_n.x, x_i0, aR[f0][0]);
            aR[f0][1]     = ffma2(w_r.x, x_r1, aR[f0][1]);
            aR[f0][1]     = ffma2(w_n.x, x_i1, aR[f0][1]);
            aI[f0][0]     = ffma2(w_r.x, x_i0, aI[f0][0]);
            aI[f0][0]     = ffma2(w_i.x, x_r0, aI[f0][0]);
            aI[f0][1]     = ffma2(w_r.x, x_i1, aI[f0][1]);
            aI[f0][1]     = ffma2(w_i.x, x_r1, aI[f0][1]);
            aR[f0+1][0]   = ffma2(w_r.y, x_r0, aR[f0+1][0]);
            aR[f0+1][0]   = ffma2(w_n.y, x_i0, aR[f0+1][0]);
            aR[f0+1][1]   = ffma2(w_r.y, x_r1, aR[f0+1][1]);
            aR[f0+1][1]   = ffma2(w_n.y, x_i1, aR[f0+1][1]);
            aI[f0+1][0]   = ffma2(w_r.y, x_i0, aI[f0+1][0]);
            aI[f0+1][0]   = ffma2(w_i.y, x_r0, aI[f0+1][0]);
            aI[f0+1][1]   = ffma2(w_r.y, x_i1, aI[f0+1][1]);
            aI[f0+1][1]   = ffma2(w_i.y, x_r1, aI[f0+1][1]);
        }
    }

    // --- epilogue: relu on real part only, write (2, B, F, L, M) ---
    const int outHalf = B_ * F_ * L_ * M_;
    #pragma unroll
    for (int fl = 0; fl < FH; ++fl) {
        const int f  = fh * FH + fl;
        const int oR = ((b * F_ + f) * L_ + l) * M_ + m0;
        float r0, r1, r2, r3, i0, i1, i2, i3;
        upk2(aR[fl][0], r0, r1); upk2(aR[fl][1], r2, r3);
        upk2(aI[fl][0], i0, i1); upk2(aI[fl][1], i2, i3);
        *(float4*)(out + oR) = make_float4(fmaxf(r0, 0.0f), fmaxf(r1, 0.0f),
                                           fmaxf(r2, 0.0f), fmaxf(r3, 0.0f));
        *(float4*)(out + outHalf + oR) = make_float4(i0, i1, i2, i3);
    }
}

extern "C" void kernel_launch(void* const* d_in, const int* in_sizes, int n_in,
                              void* d_out, int out_size) {
    const float* xr = (const float*)d_in[0];
    const float* xi = (const float*)d_in[1];
    const float* wr = (const float*)d_in[2];
    const float* wi = (const float*)d_in[3];
    float* out = (float*)d_out;
    dim3 grid(2, L_);   // (f-half, l) — f-half fastest so pairs are co-resident
    sphere_conv_kernel<<<grid, 256>>>(xr, xi, wr, wi, out);
}

// round 4
// speedup vs baseline: 1.2594x; 1.0151x over previous
#include <cuda_runtime.h>

// SphereConv R4: quarter-tiles for a single balanced wave.
// Block (128 thr) = one l x f-half(4) x m-half(128). Grid = 4 x 256 = 1024
// blocks; 7 CTAs/SM (launch_bounds cap 72 regs) -> 1036 slots, single wave,
// ~1% imbalance. 4 m/thread keeps float4 LDGs; 16 u64 accumulators.

#define B_ 4
#define C_ 32
#define L_ 256
#define M_ 256
#define F_ 8
#define N_ 64
#define FH 4     // f's per block

typedef unsigned long long u64;

__device__ __forceinline__ u64 pk2(float lo, float hi) {
    u64 r;
    asm("mov.b64 %0, {%1, %2};" : "=l"(r) : "f"(lo), "f"(hi));
    return r;
}
__device__ __forceinline__ void upk2(u64 v, float& lo, float& hi) {
    asm("mov.b64 {%0, %1}, %2;" : "=f"(lo), "=f"(hi) : "l"(v));
}
__device__ __forceinline__ u64 ffma2(u64 a, u64 b, u64 c) {
    u64 d;
    asm("fma.rn.f32x2 %0, %1, %2, %3;" : "=l"(d) : "l"(a), "l"(b), "l"(c));
    return d;
}

__global__ void __launch_bounds__(128, 7) sphere_conv_kernel(
    const float* __restrict__ xr, const float* __restrict__ xi,
    const float* __restrict__ wr, const float* __restrict__ wi,
    float* __restrict__ out)
{
    __shared__ u64 swr[C_ * FH];   // {s*wr, s*wr}
    __shared__ u64 swi[C_ * FH];   // {s*wi, s*wi}
    __shared__ u64 snw[C_ * FH];   // {-s*wi, -s*wi}

    const int fh  = blockIdx.x & 1;        // f-half
    const int mh  = blockIdx.x >> 1;       // m-half
    const int l   = blockIdx.y;
    const int tid = threadIdx.x;

    // --- weight interpolation: 128 (f_local, c) pairs == 128 threads ---
    {
        const int fl = tid >> 5;           // 0..3
        const int c  = tid & 31;           // 0..31
        const int f  = fh * FH + fl;
        float t = ((float)l / (float)(L_ - 1)) * (float)(N_ - 1);
        int lo = (int)floorf(t);
        lo = lo < 0 ? 0 : (lo > N_ - 2 ? N_ - 2 : lo);
        const float fr = t - (float)lo;
        const int base = (f * C_ + c) * N_ + lo;
        float wrv = wr[base] * (1.0f - fr) + wr[base + 1] * fr;
        float wiv = wi[base] * (1.0f - fr) + wi[base + 1] * fr;
        const float s = sqrtf(1.0f + (float)l) * (1.0f / (float)C_);
        wrv *= s; wiv *= s;
        swr[c * FH + fl] = pk2(wrv, wrv);
        swi[c * FH + fl] = pk2(wiv, wiv);
        snw[c * FH + fl] = pk2(-wiv, -wiv);
    }
    __syncthreads();

    const int b  = tid >> 5;                       // 0..3
    const int mq = tid & 31;                       // 0..31
    const int m0 = (mh << 7) + (mq << 2);          // 4 m-values per thread

    const int base4 = (((b * C_) * L_ + l) * M_ + m0) >> 2;   // float4 idx (c=0)
    const int cstr4 = (L_ * M_) >> 2;

    const float4* __restrict__ xr4 = (const float4*)xr;
    const float4* __restrict__ xi4 = (const float4*)xi;

    u64 aR[FH][2], aI[FH][2];
    #pragma unroll
    for (int f = 0; f < FH; ++f) {
        aR[f][0] = aR[f][1] = 0ull;
        aI[f][0] = aI[f][1] = 0ull;
    }

    #pragma unroll 4
    for (int c = 0; c < C_; ++c) {
        const float4 vr = __ldg(xr4 + base4 + c * cstr4);
        const float4 vi = __ldg(xi4 + base4 + c * cstr4);
        const u64 x_r0 = pk2(vr.x, vr.y), x_r1 = pk2(vr.z, vr.w);
        const u64 x_i0 = pk2(vi.x, vi.y), x_i1 = pk2(vi.z, vi.w);

        const ulonglong2* __restrict__ pwr = (const ulonglong2*)(swr + c * FH);
        const ulonglong2* __restrict__ pwi = (const ulonglong2*)(swi + c * FH);
        const ulonglong2* __restrict__ pnw = (const ulonglong2*)(snw + c * FH);

        #pragma unroll
        for (int fp = 0; fp < FH / 2; ++fp) {
            const ulonglong2 w_r = pwr[fp];
            const ulonglong2 w_i = pwi[fp];
            const ulonglong2 w_n = pnw[fp];
            const int f0 = fp * 2;
            aR[f0][0]   = ffma2(w_r.x, x_r0, aR[f0][0]);
            aR[f0][0]   = ffma2(w_n.x, x_i0, aR[f0][0]);
            aR[f0][1]   = ffma2(w_r.x, x_r1, aR[f0][1]);
            aR[f0][1]   = ffma2(w_n.x, x_i1, aR[f0][1]);
            aI[f0][0]   = ffma2(w_r.x, x_i0, aI[f0][0]);
            aI[f0][0]   = ffma2(w_i.x, x_r0, aI[f0][0]);
            aI[f0][1]   = ffma2(w_r.x, x_i1, aI[f0][1]);
            aI[f0][1]   = ffma2(w_i.x, x_r1, aI[f0][1]);
            aR[f0+1][0] = ffma2(w_r.y, x_r0, aR[f0+1][0]);
            aR[f0+1][0] = ffma2(w_n.y, x_i0, aR[f0+1][0]);
            aR[f0+1][1] = ffma2(w_r.y, x_r1, aR[f0+1][1]);
            aR[f0+1][1] = ffma2(w_n.y, x_i1, aR[f0+1][1]);
            aI[f0+1][0] = ffma2(w_r.y, x_i0, aI[f0+1][0]);
            aI[f0+1][0] = ffma2(w_i.y, x_r0, aI[f0+1][0]);
            aI[f0+1][1] = ffma2(w_r.y, x_i1, aI[f0+1][1]);
            aI[f0+1][1] = ffma2(w_i.y, x_r1, aI[f0+1][1]);
        }
    }

    // --- epilogue: relu on real part only, write (2, B, F, L, M) ---
    const int outHalf = B_ * F_ * L_ * M_;
    #pragma unroll
    for (int fl = 0; fl < FH; ++fl) {
        const int f  = fh * FH + fl;
        const int oR = ((b * F_ + f) * L_ + l) * M_ + m0;
        float r0, r1, r2, r3, i0, i1, i2, i3;
        upk2(aR[fl][0], r0, r1); upk2(aR[fl][1], r2, r3);
        upk2(aI[fl][0], i0, i1); upk2(aI[fl][1], i2, i3);
        *(float4*)(out + oR) = make_float4(fmaxf(r0, 0.0f), fmaxf(r1, 0.0f),
                                           fmaxf(r2, 0.0f), fmaxf(r3, 0.0f));
        *(float4*)(out + outHalf + oR) = make_float4(i0, i1, i2, i3);
    }
}

extern "C" void kernel_launch(void* const* d_in, const int* in_sizes, int n_in,
                              void* d_out, int out_size) {
    const float* xr = (const float*)d_in[0];
    const float* xi = (const float*)d_in[1];
    const float* wr = (const float*)d_in[2];
    const float* wi = (const float*)d_in[3];
    float* out = (float*)d_out;
    dim3 grid(4, L_);   // (fh|mh, l) — fh fastest: f-half pairs co-resident
    sphere_conv_kernel<<<grid, 128>>>(xr, xi, wr, wi, out);
}